// round 6
// baseline (speedup 1.0000x reference)
#include <cuda_runtime.h>
#include <cstdint>

#define HIDDEN 128
#define FEAT   512
#define MAX_NODES 12000

// Scratch: aggregated raw features per destination node.
__device__ float g_agg[(size_t)MAX_NODES * FEAT];
__device__ int g_idx64;

// ---------------------------------------------------------------------------
// Phase 0: zero aggregation scratch
// ---------------------------------------------------------------------------
__global__ void zero_kernel(int n4) {
    int i = blockIdx.x * blockDim.x + threadIdx.x;
    if (i < n4) reinterpret_cast<float4*>(g_agg)[i] = make_float4(0.f, 0.f, 0.f, 0.f);
}

// Phase 0b: detect edge_index dtype (int64 vs int32) from data
__global__ void detect_kernel(const long long* __restrict__ ei, long long n) {
    __shared__ int ok;
    if (threadIdx.x == 0) ok = 1;
    __syncthreads();
    long long v = ei[threadIdx.x];
    if (v < 0 || v >= n) ok = 0;
    __syncthreads();
    if (threadIdx.x == 0) g_idx64 = ok;
}

// ---------------------------------------------------------------------------
// Phase 1: edge scatter (1 warp/edge, vector atomics into L2-resident scratch)
// ---------------------------------------------------------------------------
__global__ void scatter_kernel(const float* __restrict__ x,
                               const void* __restrict__ ei, int E) {
    int gw   = (blockIdx.x * blockDim.x + threadIdx.x) >> 5;
    int lane = threadIdx.x & 31;
    if (gw >= E) return;

    long long row, col;
    if (g_idx64) {
        const long long* e64 = (const long long*)ei;
        row = e64[gw];
        col = e64[(size_t)E + gw];
    } else {
        const int* e32 = (const int*)ei;
        row = e32[gw];
        col = e32[(size_t)E + gw];
    }

    const float4* src = (const float4*)(x + (size_t)col * FEAT);
    float*        dst = g_agg + (size_t)row * FEAT;

#pragma unroll
    for (int i = 0; i < 4; ++i) {
        float4 v = src[lane + 32 * i];
        float* p = dst + (size_t)(lane + 32 * i) * 4;
        asm volatile("red.global.add.v4.f32 [%0], {%1, %2, %3, %4};"
                     :: "l"(p), "f"(v.x), "f"(v.y), "f"(v.z), "f"(v.w)
                     : "memory");
    }
}

// ---------------------------------------------------------------------------
// Phase 2: tf32 mma.sync GEMM, register-prefetch double buffer, 1 sync/iter.
// Per CTA: 128 nodes x 64 out-cols.  1D grid, heavy (vector) blocks first.
//   outBlk 0..1  (scalar): out = scalar@Wsroot.T + agg_s@Wsrel.T + bias (K=256)
//   outBlk 2..7  (vector): out = vector@Wvroot.T + agg_v@Wvrel.T       (K=768)
// 256 threads = 8 warps (4x2); warp tile 32x32 = 2x4 m16n8k8 subtiles.
// cvt.rna.tf32 applied at STS; fragment LDS reads ready tf32 bits.
// ---------------------------------------------------------------------------
#define SAS 36                 // smem row stride (floats)
#define A_TILE (128 * SAS)     // 4608 floats
#define B_TILE (64 * SAS)      // 2304 floats

#define MMA_TF32(c, a, b)                                                   \
    asm volatile("mma.sync.aligned.m16n8k8.row.col.f32.tf32.tf32.f32 "      \
                 "{%0,%1,%2,%3}, {%4,%5,%6,%7}, {%8,%9}, {%0,%1,%2,%3};"    \
                 : "+f"((c)[0]), "+f"((c)[1]), "+f"((c)[2]), "+f"((c)[3])   \
                 : "r"((a)[0]), "r"((a)[1]), "r"((a)[2]), "r"((a)[3]),      \
                   "r"((b)[0]), "r"((b)[1]))

__device__ __forceinline__ uint32_t f2tf32(float v) {
    uint32_t r;
    asm("cvt.rna.tf32.f32 %0, %1;" : "=r"(r) : "f"(v));
    return r;
}

__global__ __launch_bounds__(256, 2)
void mma_gemm_kernel(const float* __restrict__ x,
                     const float* __restrict__ Wsrel,
                     const float* __restrict__ Wsroot,
                     const float* __restrict__ bias,
                     const float* __restrict__ Wvrel,
                     const float* __restrict__ Wvroot,
                     float* __restrict__ out, int n, int nm) {
    extern __shared__ float dsm[];
    __shared__ float sbias[64];

    float* Asb[2] = { dsm,              dsm + A_TILE };
    float* Bsb[2] = { dsm + 2 * A_TILE, dsm + 2 * A_TILE + B_TILE };

    const int tid  = threadIdx.x;
    const int wid  = tid >> 5;
    const int lane = tid & 31;
    const int gid  = lane >> 2;      // 0..7
    const int tig  = lane & 3;       // 0..3
    const int wm   = wid >> 1;       // 0..3 (m-warp)
    const int wn   = wid & 1;        // 0..1 (n-warp)

    // 1D grid decode: 6 vector col-blocks per M-tile first, then 2 scalar
    const int bx = blockIdx.x;
    int outBlk, mx;
    if (bx < 6 * nm) { outBlk = 2 + bx % 6; mx = bx / 6; }
    else             { int r = bx - 6 * nm; outBlk = r & 1; mx = r >> 1; }
    const int m0   = mx * 128;
    const int col0 = outBlk * 64;

    int Khalf, ldb, aoff;
    const float* B0;
    const float* B1;
    if (outBlk < 2) {
        Khalf = 128; ldb = 128; aoff = 0;
        B0 = Wsroot + (size_t)outBlk * 64 * 128;
        B1 = Wsrel  + (size_t)outBlk * 64 * 128;
    } else {
        Khalf = 384; ldb = 384; aoff = 128;
        B0 = Wvroot + (size_t)(outBlk - 2) * 64 * 384;
        B1 = Wvrel  + (size_t)(outBlk - 2) * 64 * 384;
    }
    const int C  = (2 * Khalf) / 32;   // 8 or 24 K-chunks
    const int Ch = C / 2;

    if (tid < 64) sbias[tid] = (outBlk < 2) ? bias[col0 + tid] : 0.f;

    // loader mapping
    const int lrowA  = tid >> 1;          // 0..127, 16 floats each
    const int lcolA  = (tid & 1) * 16;
    const int lrowB  = tid >> 2;          // 0..63, 8 floats each
    const int lcolB  = (tid & 3) * 8;
    const int anode  = m0 + lrowA;

    float4 curA[4], curB[2];

    // LDG for chunk `it` into regs
    auto ldg_chunk = [&](int it, float4 (&ra)[4], float4 (&rb)[2]) {
        const int pass = (it >= Ch);
        const int kt   = (it - pass * Ch) * 32;
        const float* Ab = (pass ? (const float*)g_agg : x) + aoff;
        const bool ok   = pass || (anode < n);
        const float4* asrc = (const float4*)(Ab + (size_t)anode * FEAT + kt + lcolA);
#pragma unroll
        for (int i = 0; i < 4; ++i)
            ra[i] = ok ? asrc[i] : make_float4(0.f, 0.f, 0.f, 0.f);
        const float* Bb = pass ? B1 : B0;
        const float4* bsrc = (const float4*)(Bb + (size_t)lrowB * ldb + kt + lcolB);
#pragma unroll
        for (int i = 0; i < 2; ++i)
            rb[i] = bsrc[i];
    };

    float acc[2][4][4];
#pragma unroll
    for (int mt = 0; mt < 2; ++mt)
#pragma unroll
        for (int nt = 0; nt < 4; ++nt)
#pragma unroll
            for (int j = 0; j < 4; ++j) acc[mt][nt][j] = 0.f;

    ldg_chunk(0, curA, curB);

#pragma unroll 1
    for (int it = 0; it < C; ++it) {
        const int st = it & 1;
        // ---- STS current chunk (cvt at store) ----
        {
            uint32_t* da = (uint32_t*)&Asb[st][lrowA * SAS + lcolA];
#pragma unroll
            for (int i = 0; i < 4; ++i) {
                da[4 * i + 0] = f2tf32(curA[i].x);
                da[4 * i + 1] = f2tf32(curA[i].y);
                da[4 * i + 2] = f2tf32(curA[i].z);
                da[4 * i + 3] = f2tf32(curA[i].w);
            }
            uint32_t* db = (uint32_t*)&Bsb[st][lrowB * SAS + lcolB];
#pragma unroll
            for (int i = 0; i < 2; ++i) {
                db[4 * i + 0] = f2tf32(curB[i].x);
                db[4 * i + 1] = f2tf32(curB[i].y);
                db[4 * i + 2] = f2tf32(curB[i].z);
                db[4 * i + 3] = f2tf32(curB[i].w);
            }
        }

        // ---- prefetch next chunk into regs (hidden behind compute) ----
        float4 nxtA[4], nxtB[2];
        if (it + 1 < C) ldg_chunk(it + 1, nxtA, nxtB);

        __syncthreads();

        // ---- compute from smem stage st ----
        const uint32_t* As = (const uint32_t*)Asb[st];
        const uint32_t* Bs = (const uint32_t*)Bsb[st];
#pragma unroll
        for (int k8 = 0; k8 < 4; ++k8) {
            const int kc = k8 * 8 + tig;
            uint32_t a[2][4], b[4][2];
#pragma unroll
            for (int mt = 0; mt < 2; ++mt) {
                const int r = wm * 32 + mt * 16 + gid;
                a[mt][0] = As[r * SAS + kc];
                a[mt][1] = As[(r + 8) * SAS + kc];
                a[mt][2] = As[r * SAS + kc + 4];
                a[mt][3] = As[(r + 8) * SAS + kc + 4];
            }
#pragma unroll
            for (int nt = 0; nt < 4; ++nt) {
                const int cidx = wn * 32 + nt * 8 + gid;
                b[nt][0] = Bs[cidx * SAS + kc];
                b[nt][1] = Bs[cidx * SAS + kc + 4];
            }
#pragma unroll
            for (int mt = 0; mt < 2; ++mt)
#pragma unroll
                for (int nt = 0; nt < 4; ++nt)
                    MMA_TF32(acc[mt][nt], a[mt], b[nt]);
        }

#pragma unroll
        for (int i = 0; i < 4; ++i) curA[i] = nxtA[i];
        curB[0] = nxtB[0]; curB[1] = nxtB[1];
    }

    // ---- epilogue ----
#pragma unroll
    for (int mt = 0; mt < 2; ++mt) {
        const int r0 = m0 + wm * 32 + mt * 16 + gid;
#pragma unroll
        for (int nt = 0; nt < 4; ++nt) {
            const int cl = wn * 32 + nt * 8 + 2 * tig;
            const float b0 = sbias[cl], b1 = sbias[cl + 1];
            if (r0 < n) {
                float2 v = make_float2(acc[mt][nt][0] + b0, acc[mt][nt][1] + b1);
                *(float2*)(out + (size_t)r0 * FEAT + col0 + cl) = v;
            }
            if (r0 + 8 < n) {
                float2 v = make_float2(acc[mt][nt][2] + b0, acc[mt][nt][3] + b1);
                *(float2*)(out + (size_t)(r0 + 8) * FEAT + col0 + cl) = v;
            }
        }
    }
}

// ---------------------------------------------------------------------------
extern "C" void kernel_launch(void* const* d_in, const int* in_sizes, int n_in,
                              void* d_out, int out_size) {
    const float* x      = (const float*)d_in[0];
    const void*  ei     = d_in[1];
    const float* Wsrel  = (const float*)d_in[2];
    const float* Wsroot = (const float*)d_in[3];
    const float* bs     = (const float*)d_in[4];
    const float* Wvrel  = (const float*)d_in[5];
    const float* Wvroot = (const float*)d_in[6];
    float*       out    = (float*)d_out;

    const int n = in_sizes[0] / FEAT;        // 10000
    const int E = in_sizes[1] / 2;           // 160000

    // Phase 0
    const int n4 = n * FEAT / 4;
    zero_kernel<<<(n4 + 255) / 256, 256>>>(n4);
    detect_kernel<<<1, 64>>>((const long long*)ei, (long long)n);

    // Phase 1
    const int blocks = (E * 32 + 255) / 256;
    scatter_kernel<<<blocks, 256>>>(x, ei, E);

    // Phase 2 (tf32 mma.sync, reg-prefetch double buffer)
    const int nm    = (n + 127) / 128;                   // 79 M-tiles
    const int DSMEM = (2 * A_TILE + 2 * B_TILE) * 4;     // 55296 B
    cudaFuncSetAttribute(mma_gemm_kernel,
                         cudaFuncAttributeMaxDynamicSharedMemorySize, DSMEM);
    mma_gemm_kernel<<<8 * nm, 256, DSMEM>>>(x, Wsrel, Wsroot, bs,
                                            Wvrel, Wvroot, out, n, nm);
}

// round 7
// speedup vs baseline: 1.1154x; 1.1154x over previous
#include <cuda_runtime.h>
#include <cstdint>

#define HIDDEN 128
#define FEAT   512
#define MAX_NODES 12000

// Scratch: aggregated raw features per destination node.
__device__ float g_agg[(size_t)MAX_NODES * FEAT];
__device__ int g_idx64;

// ---------------------------------------------------------------------------
// Phase 0: zero aggregation scratch
// ---------------------------------------------------------------------------
__global__ void zero_kernel(int n4) {
    int i = blockIdx.x * blockDim.x + threadIdx.x;
    if (i < n4) reinterpret_cast<float4*>(g_agg)[i] = make_float4(0.f, 0.f, 0.f, 0.f);
}

// Phase 0b: detect edge_index dtype (int64 vs int32) from data
__global__ void detect_kernel(const long long* __restrict__ ei, long long n) {
    __shared__ int ok;
    if (threadIdx.x == 0) ok = 1;
    __syncthreads();
    long long v = ei[threadIdx.x];
    if (v < 0 || v >= n) ok = 0;
    __syncthreads();
    if (threadIdx.x == 0) g_idx64 = ok;
}

// ---------------------------------------------------------------------------
// Shared GEMM half: out_tile (+)= A_slice @ W_slice^T (+ bias)
// BM=128, BN=128, BK=32, 256 threads, 8 warps (4x2), warp tile 32x64.
// Exactly the R4-validated compute shape (single-buffered, cvt at STS).
// ---------------------------------------------------------------------------
#define SAS 36   // smem row stride (floats)

#define MMA_TF32(c, a, b)                                                   \
    asm volatile("mma.sync.aligned.m16n8k8.row.col.f32.tf32.tf32.f32 "      \
                 "{%0,%1,%2,%3}, {%4,%5,%6,%7}, {%8,%9}, {%0,%1,%2,%3};"    \
                 : "+f"((c)[0]), "+f"((c)[1]), "+f"((c)[2]), "+f"((c)[3])   \
                 : "r"((a)[0]), "r"((a)[1]), "r"((a)[2]), "r"((a)[3]),      \
                   "r"((b)[0]), "r"((b)[1]))

__device__ __forceinline__ uint32_t f2tf32(float v) {
    uint32_t r;
    asm("cvt.rna.tf32.f32 %0, %1;" : "=r"(r) : "f"(v));
    return r;
}

__device__ __forceinline__ void gemm_half(
    int mx, int by,
    const float* __restrict__ A,      // node features, FEAT stride
    const float* __restrict__ Ws,     // scalar weight 128x128
    const float* __restrict__ Wv,     // vector weight 384x384
    const float* __restrict__ bias,   // null -> zeros
    float* __restrict__ out, int n, int accum) {
    __shared__ uint32_t As[128 * SAS];
    __shared__ uint32_t Bs[128 * SAS];
    __shared__ float sbias[128];

    const int tid  = threadIdx.x;
    const int wid  = tid >> 5;
    const int lane = tid & 31;
    const int gid  = lane >> 2;
    const int tig  = lane & 3;
    const int wm   = wid >> 1;
    const int wn   = wid & 1;
    const int m0   = mx * 128;

    int Khalf, ldb, aoff;
    const float* B;
    if (by == 0) { Khalf = 128; ldb = 128; aoff = 0;   B = Ws; }
    else         { Khalf = 384; ldb = 384; aoff = 128;
                   B = Wv + (size_t)(by - 1) * 128 * 384; }
    const int C = Khalf / 32;

    if (tid < 128) sbias[tid] = (bias && by == 0) ? bias[tid] : 0.f;

    float acc[2][8][4];
#pragma unroll
    for (int mt = 0; mt < 2; ++mt)
#pragma unroll
        for (int nt = 0; nt < 8; ++nt)
#pragma unroll
            for (int j = 0; j < 4; ++j) acc[mt][nt][j] = 0.f;

    const int lrow  = tid >> 1;
    const int lcol0 = (tid & 1) * 16;

#pragma unroll 1
    for (int it = 0; it < C; ++it) {
        const int kt = it * 32;
        if (it > 0) __syncthreads();

        // A tile
        {
            const int node = m0 + lrow;
            const bool ok  = node < n;
            const float4* src = (const float4*)(A + aoff + (size_t)node * FEAT + kt + lcol0);
            uint32_t* dst = &As[lrow * SAS + lcol0];
#pragma unroll
            for (int i = 0; i < 4; ++i) {
                float4 v = ok ? src[i] : make_float4(0.f, 0.f, 0.f, 0.f);
                dst[4 * i + 0] = f2tf32(v.x);
                dst[4 * i + 1] = f2tf32(v.y);
                dst[4 * i + 2] = f2tf32(v.z);
                dst[4 * i + 3] = f2tf32(v.w);
            }
        }
        // B tile
        {
            const float4* src = (const float4*)(B + (size_t)lrow * ldb + kt + lcol0);
            uint32_t* dst = &Bs[lrow * SAS + lcol0];
#pragma unroll
            for (int i = 0; i < 4; ++i) {
                float4 v = src[i];
                dst[4 * i + 0] = f2tf32(v.x);
                dst[4 * i + 1] = f2tf32(v.y);
                dst[4 * i + 2] = f2tf32(v.z);
                dst[4 * i + 3] = f2tf32(v.w);
            }
        }
        __syncthreads();

#pragma unroll
        for (int k8 = 0; k8 < 4; ++k8) {
            const int kc = k8 * 8 + tig;
            uint32_t a[2][4], b[8][2];
#pragma unroll
            for (int mt = 0; mt < 2; ++mt) {
                const int r = wm * 32 + mt * 16 + gid;
                a[mt][0] = As[r * SAS + kc];
                a[mt][1] = As[(r + 8) * SAS + kc];
                a[mt][2] = As[r * SAS + kc + 4];
                a[mt][3] = As[(r + 8) * SAS + kc + 4];
            }
#pragma unroll
            for (int nt = 0; nt < 8; ++nt) {
                const int cidx = wn * 64 + nt * 8 + gid;
                b[nt][0] = Bs[cidx * SAS + kc];
                b[nt][1] = Bs[cidx * SAS + kc + 4];
            }
#pragma unroll
            for (int mt = 0; mt < 2; ++mt)
#pragma unroll
                for (int nt = 0; nt < 8; ++nt)
                    MMA_TF32(acc[mt][nt], a[mt], b[nt]);
        }
    }

    // epilogue
#pragma unroll
    for (int mt = 0; mt < 2; ++mt) {
        const int r0 = m0 + wm * 32 + mt * 16 + gid;
#pragma unroll
        for (int nt = 0; nt < 8; ++nt) {
            const int cl = wn * 64 + nt * 8 + 2 * tig;
            const float b0 = sbias[cl], b1 = sbias[cl + 1];
            float* p0 = out + (size_t)r0 * FEAT + by * 128 + cl;
            float* p1 = out + (size_t)(r0 + 8) * FEAT + by * 128 + cl;
            if (r0 < n) {
                float2 v = make_float2(acc[mt][nt][0] + b0, acc[mt][nt][1] + b1);
                if (accum) { float2 o = *(float2*)p0; v.x += o.x; v.y += o.y; }
                *(float2*)p0 = v;
            }
            if (r0 + 8 < n) {
                float2 v = make_float2(acc[mt][nt][2] + b0, acc[mt][nt][3] + b1);
                if (accum) { float2 o = *(float2*)p1; v.x += o.x; v.y += o.y; }
                *(float2*)p1 = v;
            }
        }
    }
}

// ---------------------------------------------------------------------------
// Phase 1 (fused): root-GEMM blocks interleaved among edge-scatter blocks.
// Scatter blocks: 8 warps, 4 edges batched per warp per iteration (MLP=16).
// ---------------------------------------------------------------------------
__global__ __launch_bounds__(256, 2)
void fused_root_scatter_kernel(const float* __restrict__ x,
                               const void* __restrict__ ei,
                               const float* __restrict__ Wsroot,
                               const float* __restrict__ Wvroot,
                               const float* __restrict__ bias,
                               float* __restrict__ out,
                               int n, int E, int ngemm, int stride, int sblocks) {
    const int bx = blockIdx.x;
    const int g  = bx / stride;
    if ((bx % stride) == 0 && g < ngemm) {
        gemm_half(g >> 2, g & 3, x, Wsroot, Wvroot, bias, out, n, 0);
        return;
    }
    // ---- scatter branch ----
    const int cnt  = min(bx / stride + 1, ngemm);
    const int sIdx = bx - cnt;
    const int wid  = threadIdx.x >> 5;
    const int lane = threadIdx.x & 31;
    const int wg   = sIdx * 8 + wid;
    const int totW = sblocks * 8;
    const int idx64 = g_idx64;
    const long long* e64 = (const long long*)ei;
    const int*       e32 = (const int*)ei;

    for (int e0 = wg * 4; e0 < E; e0 += totW * 4) {
        long long rows[4], cols[4];
#pragma unroll
        for (int i = 0; i < 4; ++i) {
            const int e = e0 + i;
            if (e < E) {
                if (idx64) { rows[i] = e64[e]; cols[i] = e64[(size_t)E + e]; }
                else       { rows[i] = e32[e]; cols[i] = e32[(size_t)E + e]; }
            } else rows[i] = -1;
        }
        // gather all data first (max MLP), then fire REDs
        float4 v[4][4];
#pragma unroll
        for (int i = 0; i < 4; ++i) {
            if (rows[i] >= 0) {
                const float4* src = (const float4*)(x + (size_t)cols[i] * FEAT);
#pragma unroll
                for (int j = 0; j < 4; ++j) v[i][j] = src[lane + 32 * j];
            }
        }
#pragma unroll
        for (int i = 0; i < 4; ++i) {
            if (rows[i] >= 0) {
                float* dst = g_agg + (size_t)rows[i] * FEAT;
#pragma unroll
                for (int j = 0; j < 4; ++j) {
                    float* p = dst + (size_t)(lane + 32 * j) * 4;
                    asm volatile("red.global.add.v4.f32 [%0], {%1, %2, %3, %4};"
                                 :: "l"(p), "f"(v[i][j].x), "f"(v[i][j].y),
                                    "f"(v[i][j].z), "f"(v[i][j].w) : "memory");
                }
            }
        }
    }
}

// ---------------------------------------------------------------------------
// Phase 2: aggregate-half GEMM, accumulates into out.
// ---------------------------------------------------------------------------
__global__ __launch_bounds__(256, 2)
void agg_gemm_kernel(const float* __restrict__ Wsrel,
                     const float* __restrict__ Wvrel,
                     float* __restrict__ out, int n) {
    gemm_half(blockIdx.x, blockIdx.y, g_agg, Wsrel, Wvrel, nullptr, out, n, 1);
}

// ---------------------------------------------------------------------------
extern "C" void kernel_launch(void* const* d_in, const int* in_sizes, int n_in,
                              void* d_out, int out_size) {
    const float* x      = (const float*)d_in[0];
    const void*  ei     = d_in[1];
    const float* Wsrel  = (const float*)d_in[2];
    const float* Wsroot = (const float*)d_in[3];
    const float* bs     = (const float*)d_in[4];
    const float* Wvrel  = (const float*)d_in[5];
    const float* Wvroot = (const float*)d_in[6];
    float*       out    = (float*)d_out;

    const int n = in_sizes[0] / FEAT;        // 10000
    const int E = in_sizes[1] / 2;           // 160000

    // Phase 0
    const int n4 = n * FEAT / 4;
    zero_kernel<<<(n4 + 255) / 256, 256>>>(n4);
    detect_kernel<<<1, 64>>>((const long long*)ei, (long long)n);

    // Phase 1: fused root-GEMM + scatter
    const int nm      = (n + 127) / 128;     // 79
    const int ngemm   = 4 * nm;              // 316
    const int sblocks = 2048;
    const int total   = ngemm + sblocks;     // 2364
    const int stride  = total / ngemm;       // 7
    fused_root_scatter_kernel<<<total, 256>>>(x, ei, Wsroot, Wvroot, bs, out,
                                              n, E, ngemm, stride, sblocks);

    // Phase 2: aggregate-half GEMM (accumulate)
    agg_gemm_kernel<<<dim3(nm, 4), 256>>>(Wsrel, Wvrel, out, n);
}

// round 8
// speedup vs baseline: 1.2231x; 1.0965x over previous
#include <cuda_runtime.h>
#include <cstdint>

#define HIDDEN 128
#define FEAT   512
#define MAX_NODES 12000

// Scratch: aggregated raw features per destination node.
__device__ float g_agg[(size_t)MAX_NODES * FEAT];
__device__ int g_idx64;

// Pre-rounded (tf32 RNA) weights: Wsroot | Wsrel | Wvroot | Wvrel
#define WSROOT_OFF 0
#define WSREL_OFF  16384
#define WVROOT_OFF 32768
#define WVREL_OFF  180224
#define WTOTAL     327680
__device__ float g_w[WTOTAL];

// ---------------------------------------------------------------------------
// Phase 0: zero aggregation scratch
// ---------------------------------------------------------------------------
__global__ void zero_kernel(int n4) {
    int i = blockIdx.x * blockDim.x + threadIdx.x;
    if (i < n4) reinterpret_cast<float4*>(g_agg)[i] = make_float4(0.f, 0.f, 0.f, 0.f);
}

// Phase 0b: detect edge_index dtype (int64 vs int32) from data
__global__ void detect_kernel(const long long* __restrict__ ei, long long n) {
    __shared__ int ok;
    if (threadIdx.x == 0) ok = 1;
    __syncthreads();
    long long v = ei[threadIdx.x];
    if (v < 0 || v >= n) ok = 0;
    __syncthreads();
    if (threadIdx.x == 0) g_idx64 = ok;
}

// Phase 0c: pre-round all weights to tf32 (RNA) once per launch
__global__ void round_w_kernel(const float* __restrict__ Wsroot,
                               const float* __restrict__ Wsrel,
                               const float* __restrict__ Wvroot,
                               const float* __restrict__ Wvrel) {
    int i = blockIdx.x * blockDim.x + threadIdx.x;
    if (i >= WTOTAL) return;
    float v;
    if      (i < WSREL_OFF)  v = Wsroot[i];
    else if (i < WVROOT_OFF) v = Wsrel[i - WSREL_OFF];
    else if (i < WVREL_OFF)  v = Wvroot[i - WVROOT_OFF];
    else                     v = Wvrel[i - WVREL_OFF];
    uint32_t r;
    asm("cvt.rna.tf32.f32 %0, %1;" : "=r"(r) : "f"(v));
    g_w[i] = __uint_as_float(r);
}

// ---------------------------------------------------------------------------
// Phase 1: edge scatter (1 warp/edge, vector atomics into L2-resident scratch)
// ---------------------------------------------------------------------------
__global__ void scatter_kernel(const float* __restrict__ x,
                               const void* __restrict__ ei, int E) {
    int gw   = (blockIdx.x * blockDim.x + threadIdx.x) >> 5;
    int lane = threadIdx.x & 31;
    if (gw >= E) return;

    long long row, col;
    if (g_idx64) {
        const long long* e64 = (const long long*)ei;
        row = e64[gw];
        col = e64[(size_t)E + gw];
    } else {
        const int* e32 = (const int*)ei;
        row = e32[gw];
        col = e32[(size_t)E + gw];
    }

    const float4* src = (const float4*)(x + (size_t)col * FEAT);
    float*        dst = g_agg + (size_t)row * FEAT;

#pragma unroll
    for (int i = 0; i < 4; ++i) {
        float4 v = src[lane + 32 * i];
        float* p = dst + (size_t)(lane + 32 * i) * 4;
        asm volatile("red.global.add.v4.f32 [%0], {%1, %2, %3, %4};"
                     :: "l"(p), "f"(v.x), "f"(v.y), "f"(v.z), "f"(v.w)
                     : "memory");
    }
}

// ---------------------------------------------------------------------------
// Phase 2: tf32 mma.sync GEMM, 3-stage cp.async pipeline, 1 sync/iter,
// NO cvt in the mainloop (weights pre-rounded; A raw bits -> tf32 truncation).
// Per CTA: 128 nodes x 128 out-cols.  1D grid, heavy (vector) blocks first.
// 256 threads = 8 warps (4x2); warp tile 32x64 = 2x8 m16n8k8 subtiles.
// ---------------------------------------------------------------------------
#define SAS 36                 // smem row stride (floats), 144B (16B-aligned)
#define TILEF (128 * SAS)      // floats per tile buffer

#define MMA_TF32(c, a, b)                                                   \
    asm volatile("mma.sync.aligned.m16n8k8.row.col.f32.tf32.tf32.f32 "      \
                 "{%0,%1,%2,%3}, {%4,%5,%6,%7}, {%8,%9}, {%0,%1,%2,%3};"    \
                 : "+f"((c)[0]), "+f"((c)[1]), "+f"((c)[2]), "+f"((c)[3])   \
                 : "r"((a)[0]), "r"((a)[1]), "r"((a)[2]), "r"((a)[3]),      \
                   "r"((b)[0]), "r"((b)[1]))

#define CP16(dst, src, sz)                                                  \
    asm volatile("cp.async.ca.shared.global [%0], [%1], 16, %2;"            \
                 :: "r"(dst), "l"(src), "r"(sz) : "memory")
#define CP_COMMIT() asm volatile("cp.async.commit_group;" ::: "memory")

__device__ __forceinline__ uint32_t smem_u32(const void* p) {
    uint32_t a;
    asm("{ .reg .u64 t; cvta.to.shared.u64 t, %1; cvt.u32.u64 %0, t; }"
        : "=r"(a) : "l"(p));
    return a;
}

__global__ __launch_bounds__(256, 2)
void mma_gemm_kernel(const float* __restrict__ x,
                     const float* __restrict__ bias,
                     float* __restrict__ out, int n, int nm) {
    extern __shared__ float dsm[];
    __shared__ float sbias[128];

    const int tid  = threadIdx.x;
    const int wid  = tid >> 5;
    const int lane = tid & 31;
    const int gid  = lane >> 2;      // 0..7
    const int tig  = lane & 3;       // 0..3
    const int wm   = wid >> 1;       // 0..3 (m-warp)
    const int wn   = wid & 1;        // 0..1 (n-warp)

    // heavy (vector) blocks first
    const int bx = blockIdx.x;
    int by, mx;
    if (bx < 3 * nm) { by = 1 + bx % 3; mx = bx / 3; }
    else             { by = 0;          mx = bx - 3 * nm; }
    const int m0 = mx * 128;

    int Khalf, ldb, aoff;
    const float* B0;
    const float* B1;
    if (by == 0) {
        Khalf = 128; ldb = 128; aoff = 0;
        B0 = g_w + WSROOT_OFF;
        B1 = g_w + WSREL_OFF;
    } else {
        Khalf = 384; ldb = 384; aoff = 128;
        B0 = g_w + WVROOT_OFF + (size_t)(by - 1) * 128 * 384;
        B1 = g_w + WVREL_OFF  + (size_t)(by - 1) * 128 * 384;
    }
    const int C  = (2 * Khalf) / 32;   // 8 or 24 K-chunks
    const int Ch = C / 2;

    if (tid < 128) sbias[tid] = (by == 0) ? bias[tid] : 0.f;

    // loader mapping: 2 threads per 32-float row, 4x 16B chunks each
    const int lrow  = tid >> 1;          // 0..127
    const int lcol0 = (tid & 1) * 16;
    const int anode = m0 + lrow;

    uint32_t sA[3], sB[3];
#pragma unroll
    for (int s = 0; s < 3; ++s) {
        sA[s] = smem_u32(&dsm[s * TILEF + lrow * SAS + lcol0]);
        sB[s] = smem_u32(&dsm[(3 + s) * TILEF + lrow * SAS + lcol0]);
    }

    // issue async loads for chunk `it` into stage `s`
    auto load_tile = [&](int s, int it) {
        const int pass = (it >= Ch);
        const int kt   = (it - pass * Ch) * 32;
        const float* Ab = (pass ? (const float*)g_agg : x) + aoff;
        const uint32_t asz = (pass || anode < n) ? 16u : 0u;
        const float* asrc = Ab + (size_t)anode * FEAT + kt + lcol0;
        const float* bsrc = (pass ? B1 : B0) + (size_t)lrow * ldb + kt + lcol0;
#pragma unroll
        for (int i = 0; i < 4; ++i)
            CP16(sA[s] + 16 * i, asrc + 4 * i, asz);
#pragma unroll
        for (int i = 0; i < 4; ++i)
            CP16(sB[s] + 16 * i, bsrc + 4 * i, 16u);
        CP_COMMIT();
    };

    float acc[2][8][4];
#pragma unroll
    for (int mt = 0; mt < 2; ++mt)
#pragma unroll
        for (int nt = 0; nt < 8; ++nt)
#pragma unroll
            for (int j = 0; j < 4; ++j) acc[mt][nt][j] = 0.f;

    // prologue: stages 0 and 1 in flight
    load_tile(0, 0);
    load_tile(1, 1);

    int st = 0;
#pragma unroll 1
    for (int it = 0; it < C; ++it) {
        asm volatile("cp.async.wait_group 1;" ::: "memory");  // stage `st` ready
        __syncthreads();  // + all warps done reading stage (it+2)%3 at it-1

        if (it + 2 < C) {
            int ws = st + 2; if (ws >= 3) ws -= 3;
            load_tile(ws, it + 2);
        }

        const uint32_t* As = (const uint32_t*)&dsm[st * TILEF];
        const uint32_t* Bs = (const uint32_t*)&dsm[(3 + st) * TILEF];
#pragma unroll
        for (int k8 = 0; k8 < 4; ++k8) {
            const int kc = k8 * 8 + tig;
            uint32_t a[2][4], b[8][2];
#pragma unroll
            for (int mt = 0; mt < 2; ++mt) {
                const int r = wm * 32 + mt * 16 + gid;
                a[mt][0] = As[r * SAS + kc];
                a[mt][1] = As[(r + 8) * SAS + kc];
                a[mt][2] = As[r * SAS + kc + 4];
                a[mt][3] = As[(r + 8) * SAS + kc + 4];
            }
#pragma unroll
            for (int nt = 0; nt < 8; ++nt) {
                const int cidx = wn * 64 + nt * 8 + gid;
                b[nt][0] = Bs[cidx * SAS + kc];
                b[nt][1] = Bs[cidx * SAS + kc + 4];
            }
#pragma unroll
            for (int mt = 0; mt < 2; ++mt)
#pragma unroll
                for (int nt = 0; nt < 8; ++nt)
                    MMA_TF32(acc[mt][nt], a[mt], b[nt]);
        }

        ++st; if (st >= 3) st = 0;
    }

    // ---- epilogue ----
#pragma unroll
    for (int mt = 0; mt < 2; ++mt) {
        const int r0 = m0 + wm * 32 + mt * 16 + gid;
#pragma unroll
        for (int nt = 0; nt < 8; ++nt) {
            const int cl = wn * 64 + nt * 8 + 2 * tig;
            const float b0 = sbias[cl], b1 = sbias[cl + 1];
            if (r0 < n) {
                float2 v = make_float2(acc[mt][nt][0] + b0, acc[mt][nt][1] + b1);
                *(float2*)(out + (size_t)r0 * FEAT + by * 128 + cl) = v;
            }
            if (r0 + 8 < n) {
                float2 v = make_float2(acc[mt][nt][2] + b0, acc[mt][nt][3] + b1);
                *(float2*)(out + (size_t)(r0 + 8) * FEAT + by * 128 + cl) = v;
            }
        }
    }
}

// ---------------------------------------------------------------------------
extern "C" void kernel_launch(void* const* d_in, const int* in_sizes, int n_in,
                              void* d_out, int out_size) {
    const float* x      = (const float*)d_in[0];
    const void*  ei     = d_in[1];
    const float* Wsrel  = (const float*)d_in[2];
    const float* Wsroot = (const float*)d_in[3];
    const float* bs     = (const float*)d_in[4];
    const float* Wvrel  = (const float*)d_in[5];
    const float* Wvroot = (const float*)d_in[6];
    float*       out    = (float*)d_out;

    const int n = in_sizes[0] / FEAT;        // 10000
    const int E = in_sizes[1] / 2;           // 160000

    // Phase 0
    const int n4 = n * FEAT / 4;
    zero_kernel<<<(n4 + 255) / 256, 256>>>(n4);
    detect_kernel<<<1, 64>>>((const long long*)ei, (long long)n);
    round_w_kernel<<<(WTOTAL + 255) / 256, 256>>>(Wsroot, Wsrel, Wvroot, Wvrel);

    // Phase 1
    const int blocks = (E * 32 + 255) / 256;
    scatter_kernel<<<blocks, 256>>>(x, ei, E);

    // Phase 2 (tf32 mma.sync, 3-stage cp.async pipeline)
    const int nm    = (n + 127) / 128;       // 79 M-tiles
    const int DSMEM = 6 * TILEF * 4;         // 110592 B
    cudaFuncSetAttribute(mma_gemm_kernel,
                         cudaFuncAttributeMaxDynamicSharedMemorySize, DSMEM);
    mma_gemm_kernel<<<4 * nm, 256, DSMEM>>>(x, bs, out, n, nm);
}

// round 11
// speedup vs baseline: 1.3823x; 1.1301x over previous
#include <cuda_runtime.h>
#include <cstdint>

#define HIDDEN 128
#define FEAT   512
#define MAX_NODES 12000
#define MAX_EDGES 200000

// Aggregated raw features per destination node (rows >= n stay 0 forever).
__device__ float g_agg[(size_t)MAX_NODES * FEAT];
__device__ int g_idx64;
// CSR scratch
__device__ int g_cnt[MAX_NODES];
__device__ int g_rowptr[MAX_NODES + 1];
__device__ int g_cursor[MAX_NODES];
__device__ int g_colidx[MAX_EDGES];

// ---------------------------------------------------------------------------
// dtype sniff: int64 vs int32 edge_index
// ---------------------------------------------------------------------------
__global__ void detect_kernel(const long long* __restrict__ ei, long long n) {
    __shared__ int ok;
    if (threadIdx.x == 0) ok = 1;
    __syncthreads();
    long long v = ei[threadIdx.x];
    if (v < 0 || v >= n) ok = 0;
    __syncthreads();
    if (threadIdx.x == 0) g_idx64 = ok;
}

__global__ void zero_cnt_kernel(int n) {
    int i = blockIdx.x * blockDim.x + threadIdx.x;
    if (i < n) g_cnt[i] = 0;
}

// ---------------------------------------------------------------------------
// CSR build: histogram of destination rows
// ---------------------------------------------------------------------------
__global__ void hist_kernel(const void* __restrict__ ei, int E) {
    int e = blockIdx.x * blockDim.x + threadIdx.x;
    if (e >= E) return;
    int row = g_idx64 ? (int)((const long long*)ei)[e] : ((const int*)ei)[e];
    atomicAdd(&g_cnt[row], 1);
}

// single-block exclusive scan over g_cnt[0..n) -> g_rowptr[0..n], g_cursor
#define CKMAX 16
__global__ void scan_kernel(int n) {
    __shared__ int spart[1024];
    const int tid = threadIdx.x;
    const int ck  = (n + 1023) / 1024;
    const int base = tid * ck;

    int tot = 0;
#pragma unroll
    for (int i = 0; i < CKMAX; ++i)
        if (i < ck && base + i < n) tot += g_cnt[base + i];
    spart[tid] = tot;
    __syncthreads();

    // Kogge-Stone inclusive scan
#pragma unroll
    for (int d = 1; d < 1024; d <<= 1) {
        int v = (tid >= d) ? spart[tid - d] : 0;
        __syncthreads();
        spart[tid] += v;
        __syncthreads();
    }
    int run = spart[tid] - tot;   // exclusive offset

#pragma unroll
    for (int i = 0; i < CKMAX; ++i) {
        if (i < ck && base + i <= n) {
            g_rowptr[base + i] = run;
            if (base + i < n) {
                g_cursor[base + i] = run;
                run += g_cnt[base + i];
            }
        }
    }
    if (tid == 1023) g_rowptr[n] = spart[1023];
}

__global__ void fill_kernel(const void* __restrict__ ei, int E) {
    int e = blockIdx.x * blockDim.x + threadIdx.x;
    if (e >= E) return;
    int row, col;
    if (g_idx64) {
        const long long* e64 = (const long long*)ei;
        row = (int)e64[e];
        col = (int)e64[(size_t)E + e];
    } else {
        const int* e32 = (const int*)ei;
        row = e32[e];
        col = e32[(size_t)E + e];
    }
    int pos = atomicAdd(&g_cursor[row], 1);
    g_colidx[pos] = col;
}

// ---------------------------------------------------------------------------
// Gather aggregation: 1 warp per node, accumulate neighbor rows in registers,
// write the 512-float row exactly once (no atomics, no pre-zeroing).
// ---------------------------------------------------------------------------
__global__ __launch_bounds__(256)
void gather_kernel(const float* __restrict__ x, int n) {
    const int node = (blockIdx.x * blockDim.x + threadIdx.x) >> 5;
    const int lane = threadIdx.x & 31;
    if (node >= n) return;

    const int s = g_rowptr[node];
    const int e = g_rowptr[node + 1];

    float4 acc[4];
#pragma unroll
    for (int j = 0; j < 4; ++j) acc[j] = make_float4(0.f, 0.f, 0.f, 0.f);

    int i = s;
    for (; i + 1 < e; i += 2) {
        const int c0 = g_colidx[i];
        const int c1 = g_colidx[i + 1];
        const float4* s0 = (const float4*)(x + (size_t)c0 * FEAT);
        const float4* s1 = (const float4*)(x + (size_t)c1 * FEAT);
        float4 v0[4], v1[4];
#pragma unroll
        for (int j = 0; j < 4; ++j) v0[j] = s0[lane + 32 * j];
#pragma unroll
        for (int j = 0; j < 4; ++j) v1[j] = s1[lane + 32 * j];
#pragma unroll
        for (int j = 0; j < 4; ++j) {
            acc[j].x += v0[j].x + v1[j].x;
            acc[j].y += v0[j].y + v1[j].y;
            acc[j].z += v0[j].z + v1[j].z;
            acc[j].w += v0[j].w + v1[j].w;
        }
    }
    if (i < e) {
        const float4* s0 = (const float4*)(x + (size_t)g_colidx[i] * FEAT);
#pragma unroll
        for (int j = 0; j < 4; ++j) {
            float4 v = s0[lane + 32 * j];
            acc[j].x += v.x; acc[j].y += v.y; acc[j].z += v.z; acc[j].w += v.w;
        }
    }

    float4* dst = (float4*)(g_agg + (size_t)node * FEAT);
#pragma unroll
    for (int j = 0; j < 4; ++j) dst[lane + 32 * j] = acc[j];
}

// ---------------------------------------------------------------------------
// GEMM: exact R4-measured shape (79.7us). BM=128,BN=128,BK=32, 256 thr,
// 8 warps (4x2), warp tile 32x64, cvt.rna.tf32 at STS, single-buffered.
// ---------------------------------------------------------------------------
#define SAS 36

#define MMA_TF32(c, a, b)                                                   \
    asm volatile("mma.sync.aligned.m16n8k8.row.col.f32.tf32.tf32.f32 "      \
                 "{%0,%1,%2,%3}, {%4,%5,%6,%7}, {%8,%9}, {%0,%1,%2,%3};"    \
                 : "+f"((c)[0]), "+f"((c)[1]), "+f"((c)[2]), "+f"((c)[3])   \
                 : "r"((a)[0]), "r"((a)[1]), "r"((a)[2]), "r"((a)[3]),      \
                   "r"((b)[0]), "r"((b)[1]))

__device__ __forceinline__ uint32_t f2tf32(float v) {
    uint32_t r;
    asm("cvt.rna.tf32.f32 %0, %1;" : "=r"(r) : "f"(v));
    return r;
}

__global__ __launch_bounds__(256, 2)
void mma_gemm_kernel(const float* __restrict__ x,
                     const float* __restrict__ Wsrel,
                     const float* __restrict__ Wsroot,
                     const float* __restrict__ bias,
                     const float* __restrict__ Wvrel,
                     const float* __restrict__ Wvroot,
                     float* __restrict__ out, int n) {
    __shared__ uint32_t As[128 * SAS];
    __shared__ uint32_t Bs[128 * SAS];
    __shared__ float sbias[128];

    const int tid  = threadIdx.x;
    const int wid  = tid >> 5;
    const int lane = tid & 31;
    const int gid  = lane >> 2;
    const int tig  = lane & 3;
    const int wm   = wid >> 1;
    const int wn   = wid & 1;
    const int by   = blockIdx.y;
    const int m0   = blockIdx.x * 128;

    int Khalf, ldb, aoff;
    const float* B0;
    const float* B1;
    if (by == 0) {
        Khalf = 128; ldb = 128; aoff = 0;
        B0 = Wsroot; B1 = Wsrel;
    } else {
        Khalf = 384; ldb = 384; aoff = 128;
        B0 = Wvroot + (size_t)(by - 1) * 128 * 384;
        B1 = Wvrel  + (size_t)(by - 1) * 128 * 384;
    }
    const int C  = (2 * Khalf) / 32;
    const int Ch = C / 2;

    if (tid < 128) sbias[tid] = (by == 0) ? bias[tid] : 0.f;

    float acc[2][8][4];
#pragma unroll
    for (int mt = 0; mt < 2; ++mt)
#pragma unroll
        for (int nt = 0; nt < 8; ++nt)
#pragma unroll
            for (int j = 0; j < 4; ++j) acc[mt][nt][j] = 0.f;

    const int lrow  = tid >> 1;
    const int lcol0 = (tid & 1) * 16;

#pragma unroll 1
    for (int it = 0; it < C; ++it) {
        const int pass = (it >= Ch);
        const int kt   = (it - pass * Ch) * 32;

        if (it > 0) __syncthreads();

        // A tile
        {
            const float* Ab = (pass ? (const float*)g_agg : x) + aoff;
            const int node  = m0 + lrow;
            const bool ok   = pass ? true : (node < n);
            const float4* src = (const float4*)(Ab + (size_t)node * FEAT + kt + lcol0);
            uint32_t* dst = &As[lrow * SAS + lcol0];
#pragma unroll
            for (int i = 0; i < 4; ++i) {
                float4 v = ok ? src[i] : make_float4(0.f, 0.f, 0.f, 0.f);
                dst[4 * i + 0] = f2tf32(v.x);
                dst[4 * i + 1] = f2tf32(v.y);
                dst[4 * i + 2] = f2tf32(v.z);
                dst[4 * i + 3] = f2tf32(v.w);
            }
        }
        // B tile
        {
            const float* Bb = pass ? B1 : B0;
            const float4* src = (const float4*)(Bb + (size_t)lrow * ldb + kt + lcol0);
            uint32_t* dst = &Bs[lrow * SAS + lcol0];
#pragma unroll
            for (int i = 0; i < 4; ++i) {
                float4 v = src[i];
                dst[4 * i + 0] = f2tf32(v.x);
                dst[4 * i + 1] = f2tf32(v.y);
                dst[4 * i + 2] = f2tf32(v.z);
                dst[4 * i + 3] = f2tf32(v.w);
            }
        }
        __syncthreads();

#pragma unroll
        for (int k8 = 0; k8 < 4; ++k8) {
            const int kc = k8 * 8 + tig;
            uint32_t a[2][4], b[8][2];
#pragma unroll
            for (int mt = 0; mt < 2; ++mt) {
                const int r = wm * 32 + mt * 16 + gid;
                a[mt][0] = As[r * SAS + kc];
                a[mt][1] = As[(r + 8) * SAS + kc];
                a[mt][2] = As[r * SAS + kc + 4];
                a[mt][3] = As[(r + 8) * SAS + kc + 4];
            }
#pragma unroll
            for (int nt = 0; nt < 8; ++nt) {
                const int cidx = wn * 64 + nt * 8 + gid;
                b[nt][0] = Bs[cidx * SAS + kc];
                b[nt][1] = Bs[cidx * SAS + kc + 4];
            }
#pragma unroll
            for (int mt = 0; mt < 2; ++mt)
#pragma unroll
                for (int nt = 0; nt < 8; ++nt)
                    MMA_TF32(acc[mt][nt], a[mt], b[nt]);
        }
    }

    // epilogue
#pragma unroll
    for (int mt = 0; mt < 2; ++mt) {
        const int r0 = m0 + wm * 32 + mt * 16 + gid;
#pragma unroll
        for (int nt = 0; nt < 8; ++nt) {
            const int cl = wn * 64 + nt * 8 + 2 * tig;
            const float b0 = sbias[cl], b1 = sbias[cl + 1];
            if (r0 < n) {
                float2 v = make_float2(acc[mt][nt][0] + b0, acc[mt][nt][1] + b1);
                *(float2*)(out + (size_t)r0 * FEAT + by * 128 + cl) = v;
            }
            if (r0 + 8 < n) {
                float2 v = make_float2(acc[mt][nt][2] + b0, acc[mt][nt][3] + b1);
                *(float2*)(out + (size_t)(r0 + 8) * FEAT + by * 128 + cl) = v;
            }
        }
    }
}

// ---------------------------------------------------------------------------
extern "C" void kernel_launch(void* const* d_in, const int* in_sizes, int n_in,
                              void* d_out, int out_size) {
    const float* x      = (const float*)d_in[0];
    const void*  ei     = d_in[1];
    const float* Wsrel  = (const float*)d_in[2];
    const float* Wsroot = (const float*)d_in[3];
    const float* bs     = (const float*)d_in[4];
    const float* Wvrel  = (const float*)d_in[5];
    const float* Wvroot = (const float*)d_in[6];
    float*       out    = (float*)d_out;

    const int n = in_sizes[0] / FEAT;        // 10000
    const int E = in_sizes[1] / 2;           // 160000

    // CSR build
    detect_kernel<<<1, 64>>>((const long long*)ei, (long long)n);
    zero_cnt_kernel<<<(n + 255) / 256, 256>>>(n);
    hist_kernel<<<(E + 255) / 256, 256>>>(ei, E);
    scan_kernel<<<1, 1024>>>(n);
    fill_kernel<<<(E + 255) / 256, 256>>>(ei, E);

    // Gather aggregation (1 warp / node)
    gather_kernel<<<(n * 32 + 255) / 256, 256>>>(x, n);

    // GEMM (R4 shape)
    dim3 grid((n + 127) / 128, 4);
    mma_gemm_kernel<<<grid, 256>>>(x, Wsrel, Wsroot, bs, Wvrel, Wvroot, out, n);
}

// round 12
// speedup vs baseline: 1.3999x; 1.0128x over previous
#include <cuda_runtime.h>
#include <cstdint>

#define HIDDEN 128
#define FEAT   512
#define MAX_NODES 12000
#define MAX_EDGES 200000

// Aggregated raw features per destination node (rows >= n stay 0 forever).
__device__ float g_agg[(size_t)MAX_NODES * FEAT];
__device__ int g_idx64;
// CSR scratch
__device__ int g_cnt[MAX_NODES];
__device__ int g_rowptr[MAX_NODES + 1];
__device__ int g_cursor[MAX_NODES];
__device__ int g_colidx[MAX_EDGES];

// ---------------------------------------------------------------------------
// prep: zero g_cnt everywhere; block 0 additionally sniffs edge dtype
// (int64 indices are all in [0,n); int32 reinterpreted as int64 is not).
// ---------------------------------------------------------------------------
__global__ void prep_kernel(const long long* __restrict__ ei, long long n,
                            int nn) {
    __shared__ int sok[64];
    const int i = blockIdx.x * blockDim.x + threadIdx.x;
    if (i < nn) g_cnt[i] = 0;
    if (blockIdx.x == 0 && threadIdx.x < 64) {
        long long v = ei[threadIdx.x];
        sok[threadIdx.x] = (v >= 0 && v < n) ? 1 : 0;
    }
    __syncthreads();
    if (blockIdx.x == 0 && threadIdx.x == 0) {
        int ok = 1;
#pragma unroll
        for (int j = 0; j < 64; ++j) ok &= sok[j];
        g_idx64 = ok;
    }
}

// ---------------------------------------------------------------------------
// CSR build: histogram of destination rows
// ---------------------------------------------------------------------------
__global__ void hist_kernel(const void* __restrict__ ei, int E) {
    int e = blockIdx.x * blockDim.x + threadIdx.x;
    if (e >= E) return;
    int row = g_idx64 ? (int)((const long long*)ei)[e] : ((const int*)ei)[e];
    atomicAdd(&g_cnt[row], 1);
}

// ---------------------------------------------------------------------------
// single-block exclusive scan, shuffle-based (2 barriers total)
// ---------------------------------------------------------------------------
#define CKMAX 16
__global__ void scan_kernel(int n) {
    __shared__ int wsum[32];
    const int tid  = threadIdx.x;           // 0..1023
    const int lane = tid & 31;
    const int wz   = tid >> 5;
    const int ck   = (n + 1023) / 1024;
    const int base = tid * ck;

    int vals[CKMAX];
    int tot = 0;
#pragma unroll
    for (int i = 0; i < CKMAX; ++i) {
        const int idx = base + i;
        vals[i] = (i < ck && idx < n) ? g_cnt[idx] : 0;
        tot += vals[i];
    }

    // warp inclusive scan of thread totals
    int s = tot;
#pragma unroll
    for (int d = 1; d < 32; d <<= 1) {
        int t = __shfl_up_sync(0xFFFFFFFFu, s, d);
        if (lane >= d) s += t;
    }
    if (lane == 31) wsum[wz] = s;
    __syncthreads();
    if (wz == 0) {
        int w = wsum[lane];
#pragma unroll
        for (int d = 1; d < 32; d <<= 1) {
            int t = __shfl_up_sync(0xFFFFFFFFu, w, d);
            if (lane >= d) w += t;
        }
        wsum[lane] = w;
    }
    __syncthreads();

    int run = (s - tot) + (wz ? wsum[wz - 1] : 0);   // exclusive chunk offset
#pragma unroll
    for (int i = 0; i < CKMAX; ++i) {
        const int idx = base + i;
        if (i < ck && idx < n) {
            g_rowptr[idx] = run;
            g_cursor[idx] = run;
            run += vals[i];
        }
    }
    if (tid == 1023) g_rowptr[n] = run;   // == total edge count
}

__global__ void fill_kernel(const void* __restrict__ ei, int E) {
    int e = blockIdx.x * blockDim.x + threadIdx.x;
    if (e >= E) return;
    int row, col;
    if (g_idx64) {
        const long long* e64 = (const long long*)ei;
        row = (int)e64[e];
        col = (int)e64[(size_t)E + e];
    } else {
        const int* e32 = (const int*)ei;
        row = e32[e];
        col = e32[(size_t)E + e];
    }
    int pos = atomicAdd(&g_cursor[row], 1);
    g_colidx[pos] = col;
}

// ---------------------------------------------------------------------------
// Gather aggregation: 1 warp per node, accumulate neighbor rows in registers,
// write the 512-float row exactly once (no atomics, no pre-zeroing).
// ---------------------------------------------------------------------------
__global__ __launch_bounds__(256)
void gather_kernel(const float* __restrict__ x, int n) {
    const int node = (blockIdx.x * blockDim.x + threadIdx.x) >> 5;
    const int lane = threadIdx.x & 31;
    if (node >= n) return;

    const int s = g_rowptr[node];
    const int e = g_rowptr[node + 1];

    float4 acc[4];
#pragma unroll
    for (int j = 0; j < 4; ++j) acc[j] = make_float4(0.f, 0.f, 0.f, 0.f);

    int i = s;
    for (; i + 1 < e; i += 2) {
        const int c0 = g_colidx[i];
        const int c1 = g_colidx[i + 1];
        const float4* s0 = (const float4*)(x + (size_t)c0 * FEAT);
        const float4* s1 = (const float4*)(x + (size_t)c1 * FEAT);
        float4 v0[4], v1[4];
#pragma unroll
        for (int j = 0; j < 4; ++j) v0[j] = s0[lane + 32 * j];
#pragma unroll
        for (int j = 0; j < 4; ++j) v1[j] = s1[lane + 32 * j];
#pragma unroll
        for (int j = 0; j < 4; ++j) {
            acc[j].x += v0[j].x + v1[j].x;
            acc[j].y += v0[j].y + v1[j].y;
            acc[j].z += v0[j].z + v1[j].z;
            acc[j].w += v0[j].w + v1[j].w;
        }
    }
    if (i < e) {
        const float4* s0 = (const float4*)(x + (size_t)g_colidx[i] * FEAT);
#pragma unroll
        for (int j = 0; j < 4; ++j) {
            float4 v = s0[lane + 32 * j];
            acc[j].x += v.x; acc[j].y += v.y; acc[j].z += v.z; acc[j].w += v.w;
        }
    }

    float4* dst = (float4*)(g_agg + (size_t)node * FEAT);
#pragma unroll
    for (int j = 0; j < 4; ++j) dst[lane + 32 * j] = acc[j];
}

// ---------------------------------------------------------------------------
// GEMM: exact R4-measured shape. BM=128,BN=128,BK=32, 256 thr,
// 8 warps (4x2), warp tile 32x64, cvt.rna.tf32 at STS, single-buffered.
// ---------------------------------------------------------------------------
#define SAS 36

#define MMA_TF32(c, a, b)                                                   \
    asm volatile("mma.sync.aligned.m16n8k8.row.col.f32.tf32.tf32.f32 "      \
                 "{%0,%1,%2,%3}, {%4,%5,%6,%7}, {%8,%9}, {%0,%1,%2,%3};"    \
                 : "+f"((c)[0]), "+f"((c)[1]), "+f"((c)[2]), "+f"((c)[3])   \
                 : "r"((a)[0]), "r"((a)[1]), "r"((a)[2]), "r"((a)[3]),      \
                   "r"((b)[0]), "r"((b)[1]))

__device__ __forceinline__ uint32_t f2tf32(float v) {
    uint32_t r;
    asm("cvt.rna.tf32.f32 %0, %1;" : "=r"(r) : "f"(v));
    return r;
}

__global__ __launch_bounds__(256, 2)
void mma_gemm_kernel(const float* __restrict__ x,
                     const float* __restrict__ Wsrel,
                     const float* __restrict__ Wsroot,
                     const float* __restrict__ bias,
                     const float* __restrict__ Wvrel,
                     const float* __restrict__ Wvroot,
                     float* __restrict__ out, int n) {
    __shared__ uint32_t As[128 * SAS];
    __shared__ uint32_t Bs[128 * SAS];
    __shared__ float sbias[128];

    const int tid  = threadIdx.x;
    const int wid  = tid >> 5;
    const int lane = tid & 31;
    const int gid  = lane >> 2;
    const int tig  = lane & 3;
    const int wm   = wid >> 1;
    const int wn   = wid & 1;
    const int by   = blockIdx.y;
    const int m0   = blockIdx.x * 128;

    int Khalf, ldb, aoff;
    const float* B0;
    const float* B1;
    if (by == 0) {
        Khalf = 128; ldb = 128; aoff = 0;
        B0 = Wsroot; B1 = Wsrel;
    } else {
        Khalf = 384; ldb = 384; aoff = 128;
        B0 = Wvroot + (size_t)(by - 1) * 128 * 384;
        B1 = Wvrel  + (size_t)(by - 1) * 128 * 384;
    }
    const int C  = (2 * Khalf) / 32;
    const int Ch = C / 2;

    if (tid < 128) sbias[tid] = (by == 0) ? bias[tid] : 0.f;

    float acc[2][8][4];
#pragma unroll
    for (int mt = 0; mt < 2; ++mt)
#pragma unroll
        for (int nt = 0; nt < 8; ++nt)
#pragma unroll
            for (int j = 0; j < 4; ++j) acc[mt][nt][j] = 0.f;

    const int lrow  = tid >> 1;
    const int lcol0 = (tid & 1) * 16;

#pragma unroll 1
    for (int it = 0; it < C; ++it) {
        const int pass = (it >= Ch);
        const int kt   = (it - pass * Ch) * 32;

        if (it > 0) __syncthreads();

        // A tile
        {
            const float* Ab = (pass ? (const float*)g_agg : x) + aoff;
            const int node  = m0 + lrow;
            const bool ok   = pass ? true : (node < n);
            const float4* src = (const float4*)(Ab + (size_t)node * FEAT + kt + lcol0);
            uint32_t* dst = &As[lrow * SAS + lcol0];
#pragma unroll
            for (int i = 0; i < 4; ++i) {
                float4 v = ok ? src[i] : make_float4(0.f, 0.f, 0.f, 0.f);
                dst[4 * i + 0] = f2tf32(v.x);
                dst[4 * i + 1] = f2tf32(v.y);
                dst[4 * i + 2] = f2tf32(v.z);
                dst[4 * i + 3] = f2tf32(v.w);
            }
        }
        // B tile
        {
            const float* Bb = pass ? B1 : B0;
            const float4* src = (const float4*)(Bb + (size_t)lrow * ldb + kt + lcol0);
            uint32_t* dst = &Bs[lrow * SAS + lcol0];
#pragma unroll
            for (int i = 0; i < 4; ++i) {
                float4 v = src[i];
                dst[4 * i + 0] = f2tf32(v.x);
                dst[4 * i + 1] = f2tf32(v.y);
                dst[4 * i + 2] = f2tf32(v.z);
                dst[4 * i + 3] = f2tf32(v.w);
            }
        }
        __syncthreads();

#pragma unroll
        for (int k8 = 0; k8 < 4; ++k8) {
            const int kc = k8 * 8 + tig;
            uint32_t a[2][4], b[8][2];
#pragma unroll
            for (int mt = 0; mt < 2; ++mt) {
                const int r = wm * 32 + mt * 16 + gid;
                a[mt][0] = As[r * SAS + kc];
                a[mt][1] = As[(r + 8) * SAS + kc];
                a[mt][2] = As[r * SAS + kc + 4];
                a[mt][3] = As[(r + 8) * SAS + kc + 4];
            }
#pragma unroll
            for (int nt = 0; nt < 8; ++nt) {
                const int cidx = wn * 64 + nt * 8 + gid;
                b[nt][0] = Bs[cidx * SAS + kc];
                b[nt][1] = Bs[cidx * SAS + kc + 4];
            }
#pragma unroll
            for (int mt = 0; mt < 2; ++mt)
#pragma unroll
                for (int nt = 0; nt < 8; ++nt)
                    MMA_TF32(acc[mt][nt], a[mt], b[nt]);
        }
    }

    // epilogue
#pragma unroll
    for (int mt = 0; mt < 2; ++mt) {
        const int r0 = m0 + wm * 32 + mt * 16 + gid;
#pragma unroll
        for (int nt = 0; nt < 8; ++nt) {
            const int cl = wn * 64 + nt * 8 + 2 * tig;
            const float b0 = sbias[cl], b1 = sbias[cl + 1];
            if (r0 < n) {
                float2 v = make_float2(acc[mt][nt][0] + b0, acc[mt][nt][1] + b1);
                *(float2*)(out + (size_t)r0 * FEAT + by * 128 + cl) = v;
            }
            if (r0 + 8 < n) {
                float2 v = make_float2(acc[mt][nt][2] + b0, acc[mt][nt][3] + b1);
                *(float2*)(out + (size_t)(r0 + 8) * FEAT + by * 128 + cl) = v;
            }
        }
    }
}

// ---------------------------------------------------------------------------
extern "C" void kernel_launch(void* const* d_in, const int* in_sizes, int n_in,
                              void* d_out, int out_size) {
    const float* x      = (const float*)d_in[0];
    const void*  ei     = d_in[1];
    const float* Wsrel  = (const float*)d_in[2];
    const float* Wsroot = (const float*)d_in[3];
    const float* bs     = (const float*)d_in[4];
    const float* Wvrel  = (const float*)d_in[5];
    const float* Wvroot = (const float*)d_in[6];
    float*       out    = (float*)d_out;

    const int n = in_sizes[0] / FEAT;        // 10000
    const int E = in_sizes[1] / 2;           // 160000

    // CSR build
    prep_kernel<<<(n + 255) / 256, 256>>>((const long long*)ei, (long long)n, n);
    hist_kernel<<<(E + 255) / 256, 256>>>(ei, E);
    scan_kernel<<<1, 1024>>>(n);
    fill_kernel<<<(E + 255) / 256, 256>>>(ei, E);

    // Gather aggregation (1 warp / node)
    gather_kernel<<<(n * 32 + 255) / 256, 256>>>(x, n);

    // GEMM (R4 shape)
    dim3 grid((n + 127) / 128, 4);
    mma_gemm_kernel<<<grid, 256>>>(x, Wsrel, Wsroot, bs, Wvrel, Wvroot, out, n);
}

// round 14
// speedup vs baseline: 1.5519x; 1.1085x over previous
#include <cuda_runtime.h>
#include <cstdint>

#define HIDDEN 128
#define FEAT   512
#define MAX_NODES 12000
#define MAX_EDGES 200000

// Aggregated raw features per destination node (rows >= n stay 0 forever).
__device__ float g_agg[(size_t)MAX_NODES * FEAT];
__device__ int g_idx64;
// CSR scratch
__device__ int g_cnt[MAX_NODES];
__device__ int g_rowptr[MAX_NODES + 1];
__device__ int g_cursor[MAX_NODES];
__device__ int g_colidx[MAX_EDGES];

// ---------------------------------------------------------------------------
// prep: zero g_cnt everywhere; block 0 additionally sniffs edge dtype
// ---------------------------------------------------------------------------
__global__ void prep_kernel(const long long* __restrict__ ei, long long n,
                            int nn) {
    __shared__ int sok[64];
    const int i = blockIdx.x * blockDim.x + threadIdx.x;
    if (i < nn) g_cnt[i] = 0;
    if (blockIdx.x == 0 && threadIdx.x < 64) {
        long long v = ei[threadIdx.x];
        sok[threadIdx.x] = (v >= 0 && v < n) ? 1 : 0;
    }
    __syncthreads();
    if (blockIdx.x == 0 && threadIdx.x == 0) {
        int ok = 1;
#pragma unroll
        for (int j = 0; j < 64; ++j) ok &= sok[j];
        g_idx64 = ok;
    }
}

// ---------------------------------------------------------------------------
// CSR build: histogram of destination rows (4 edges per thread)
// ---------------------------------------------------------------------------
__global__ void hist_kernel(const void* __restrict__ ei, int E) {
    const int t = blockIdx.x * blockDim.x + threadIdx.x;
    const int idx64 = g_idx64;
    const long long* e64 = (const long long*)ei;
    const int*       e32 = (const int*)ei;
    int rows[4];
#pragma unroll
    for (int i = 0; i < 4; ++i) {
        const int e = t * 4 + i;
        rows[i] = (e < E) ? (idx64 ? (int)e64[e] : e32[e]) : -1;
    }
#pragma unroll
    for (int i = 0; i < 4; ++i)
        if (rows[i] >= 0) atomicAdd(&g_cnt[rows[i]], 1);
}

// ---------------------------------------------------------------------------
// single-block exclusive scan, shuffle-based (2 barriers total)
// ---------------------------------------------------------------------------
#define CKMAX 16
__global__ void scan_kernel(int n) {
    __shared__ int wsum[32];
    const int tid  = threadIdx.x;
    const int lane = tid & 31;
    const int wz   = tid >> 5;
    const int ck   = (n + 1023) / 1024;
    const int base = tid * ck;

    int vals[CKMAX];
    int tot = 0;
#pragma unroll
    for (int i = 0; i < CKMAX; ++i) {
        const int idx = base + i;
        vals[i] = (i < ck && idx < n) ? g_cnt[idx] : 0;
        tot += vals[i];
    }

    int s = tot;
#pragma unroll
    for (int d = 1; d < 32; d <<= 1) {
        int t = __shfl_up_sync(0xFFFFFFFFu, s, d);
        if (lane >= d) s += t;
    }
    if (lane == 31) wsum[wz] = s;
    __syncthreads();
    if (wz == 0) {
        int w = wsum[lane];
#pragma unroll
        for (int d = 1; d < 32; d <<= 1) {
            int t = __shfl_up_sync(0xFFFFFFFFu, w, d);
            if (lane >= d) w += t;
        }
        wsum[lane] = w;
    }
    __syncthreads();

    int run = (s - tot) + (wz ? wsum[wz - 1] : 0);
#pragma unroll
    for (int i = 0; i < CKMAX; ++i) {
        const int idx = base + i;
        if (i < ck && idx < n) {
            g_rowptr[idx] = run;
            g_cursor[idx] = run;
            run += vals[i];
        }
    }
    if (tid == 1023) g_rowptr[n] = run;
}

// ---------------------------------------------------------------------------
// fill: 4 edges per thread, indices loaded up-front (MLP on the atomic chain)
// ---------------------------------------------------------------------------
__global__ void fill_kernel(const void* __restrict__ ei, int E) {
    const int t = blockIdx.x * blockDim.x + threadIdx.x;
    const int idx64 = g_idx64;
    const long long* e64 = (const long long*)ei;
    const int*       e32 = (const int*)ei;
    int rows[4], cols[4];
#pragma unroll
    for (int i = 0; i < 4; ++i) {
        const int e = t * 4 + i;
        if (e < E) {
            if (idx64) { rows[i] = (int)e64[e]; cols[i] = (int)e64[(size_t)E + e]; }
            else       { rows[i] = e32[e];      cols[i] = e32[(size_t)E + e]; }
        } else rows[i] = -1;
    }
    int pos[4];
#pragma unroll
    for (int i = 0; i < 4; ++i)
        if (rows[i] >= 0) pos[i] = atomicAdd(&g_cursor[rows[i]], 1);
#pragma unroll
    for (int i = 0; i < 4; ++i)
        if (rows[i] >= 0) g_colidx[pos[i]] = cols[i];
}

// ---------------------------------------------------------------------------
// Gather aggregation: 1 warp per node (unchanged, measured-good)
// ---------------------------------------------------------------------------
__global__ __launch_bounds__(256)
void gather_kernel(const float* __restrict__ x, int n) {
    const int node = (blockIdx.x * blockDim.x + threadIdx.x) >> 5;
    const int lane = threadIdx.x & 31;
    if (node >= n) return;

    const int s = g_rowptr[node];
    const int e = g_rowptr[node + 1];

    float4 acc[4];
#pragma unroll
    for (int j = 0; j < 4; ++j) acc[j] = make_float4(0.f, 0.f, 0.f, 0.f);

    int i = s;
    for (; i + 1 < e; i += 2) {
        const int c0 = g_colidx[i];
        const int c1 = g_colidx[i + 1];
        const float4* s0 = (const float4*)(x + (size_t)c0 * FEAT);
        const float4* s1 = (const float4*)(x + (size_t)c1 * FEAT);
        float4 v0[4], v1[4];
#pragma unroll
        for (int j = 0; j < 4; ++j) v0[j] = s0[lane + 32 * j];
#pragma unroll
        for (int j = 0; j < 4; ++j) v1[j] = s1[lane + 32 * j];
#pragma unroll
        for (int j = 0; j < 4; ++j) {
            acc[j].x += v0[j].x + v1[j].x;
            acc[j].y += v0[j].y + v1[j].y;
            acc[j].z += v0[j].z + v1[j].z;
            acc[j].w += v0[j].w + v1[j].w;
        }
    }
    if (i < e) {
        const float4* s0 = (const float4*)(x + (size_t)g_colidx[i] * FEAT);
#pragma unroll
        for (int j = 0; j < 4; ++j) {
            float4 v = s0[lane + 32 * j];
            acc[j].x += v.x; acc[j].y += v.y; acc[j].z += v.z; acc[j].w += v.w;
        }
    }

    float4* dst = (float4*)(g_agg + (size_t)node * FEAT);
#pragma unroll
    for (int j = 0; j < 4; ++j) dst[lane + 32 * j] = acc[j];
}

// ---------------------------------------------------------------------------
// GEMM: exact R4-measured compute shape; 1D grid with HEAVY (vector, K=768)
// blocks launched first so the straggler wave holds only short scalar CTAs.
// ---------------------------------------------------------------------------
#define SAS 36

#define MMA_TF32(c, a, b)                                                   \
    asm volatile("mma.sync.aligned.m16n8k8.row.col.f32.tf32.tf32.f32 "      \
                 "{%0,%1,%2,%3}, {%4,%5,%6,%7}, {%8,%9}, {%0,%1,%2,%3};"    \
                 : "+f"((c)[0]), "+f"((c)[1]), "+f"((c)[2]), "+f"((c)[3])   \
                 : "r"((a)[0]), "r"((a)[1]), "r"((a)[2]), "r"((a)[3]),      \
                   "r"((b)[0]), "r"((b)[1]))

__device__ __forceinline__ uint32_t f2tf32(float v) {
    uint32_t r;
    asm("cvt.rna.tf32.f32 %0, %1;" : "=r"(r) : "f"(v));
    return r;
}

__global__ __launch_bounds__(256, 2)
void mma_gemm_kernel(const float* __restrict__ x,
                     const float* __restrict__ Wsrel,
                     const float* __restrict__ Wsroot,
                     const float* __restrict__ bias,
                     const float* __restrict__ Wvrel,
                     const float* __restrict__ Wvroot,
                     float* __restrict__ out, int n, int nm) {
    __shared__ uint32_t As[128 * SAS];
    __shared__ uint32_t Bs[128 * SAS];
    __shared__ float sbias[128];

    const int tid  = threadIdx.x;
    const int wid  = tid >> 5;
    const int lane = tid & 31;
    const int gid  = lane >> 2;
    const int tig  = lane & 3;
    const int wm   = wid >> 1;
    const int wn   = wid & 1;

    // heavy (vector) blocks first
    const int bx = blockIdx.x;
    int by, mx;
    if (bx < 3 * nm) { by = 1 + bx % 3; mx = bx / 3; }
    else             { by = 0;          mx = bx - 3 * nm; }
    const int m0 = mx * 128;

    int Khalf, ldb, aoff;
    const float* B0;
    const float* B1;
    if (by == 0) {
        Khalf = 128; ldb = 128; aoff = 0;
        B0 = Wsroot; B1 = Wsrel;
    } else {
        Khalf = 384; ldb = 384; aoff = 128;
        B0 = Wvroot + (size_t)(by - 1) * 128 * 384;
        B1 = Wvrel  + (size_t)(by - 1) * 128 * 384;
    }
    const int C  = (2 * Khalf) / 32;
    const int Ch = C / 2;

    if (tid < 128) sbias[tid] = (by == 0) ? bias[tid] : 0.f;

    float acc[2][8][4];
#pragma unroll
    for (int mt = 0; mt < 2; ++mt)
#pragma unroll
        for (int nt = 0; nt < 8; ++nt)
#pragma unroll
            for (int j = 0; j < 4; ++j) acc[mt][nt][j] = 0.f;

    const int lrow  = tid >> 1;
    const int lcol0 = (tid & 1) * 16;

#pragma unroll 1
    for (int it = 0; it < C; ++it) {
        const int pass = (it >= Ch);
        const int kt   = (it - pass * Ch) * 32;

        if (it > 0) __syncthreads();

        // A tile
        {
            const float* Ab = (pass ? (const float*)g_agg : x) + aoff;
            const int node  = m0 + lrow;
            const bool ok   = pass ? true : (node < n);
            const float4* src = (const float4*)(Ab + (size_t)node * FEAT + kt + lcol0);
            uint32_t* dst = &As[lrow * SAS + lcol0];
#pragma unroll
            for (int i = 0; i < 4; ++i) {
                float4 v = ok ? src[i] : make_float4(0.f, 0.f, 0.f, 0.f);
                dst[4 * i + 0] = f2tf32(v.x);
                dst[4 * i + 1] = f2tf32(v.y);
                dst[4 * i + 2] = f2tf32(v.z);
                dst[4 * i + 3] = f2tf32(v.w);
            }
        }
        // B tile
        {
            const float* Bb = pass ? B1 : B0;
            const float4* src = (const float4*)(Bb + (size_t)lrow * ldb + kt + lcol0);
            uint32_t* dst = &Bs[lrow * SAS + lcol0];
#pragma unroll
            for (int i = 0; i < 4; ++i) {
                float4 v = src[i];
                dst[4 * i + 0] = f2tf32(v.x);
                dst[4 * i + 1] = f2tf32(v.y);
                dst[4 * i + 2] = f2tf32(v.z);
                dst[4 * i + 3] = f2tf32(v.w);
            }
        }
        __syncthreads();

#pragma unroll
        for (int k8 = 0; k8 < 4; ++k8) {
            const int kc = k8 * 8 + tig;
            uint32_t a[2][4], b[8][2];
#pragma unroll
            for (int mt = 0; mt < 2; ++mt) {
                const int r = wm * 32 + mt * 16 + gid;
                a[mt][0] = As[r * SAS + kc];
                a[mt][1] = As[(r + 8) * SAS + kc];
                a[mt][2] = As[r * SAS + kc + 4];
                a[mt][3] = As[(r + 8) * SAS + kc + 4];
            }
#pragma unroll
            for (int nt = 0; nt < 8; ++nt) {
                const int cidx = wn * 64 + nt * 8 + gid;
                b[nt][0] = Bs[cidx * SAS + kc];
                b[nt][1] = Bs[cidx * SAS + kc + 4];
            }
#pragma unroll
            for (int mt = 0; mt < 2; ++mt)
#pragma unroll
                for (int nt = 0; nt < 8; ++nt)
                    MMA_TF32(acc[mt][nt], a[mt], b[nt]);
        }
    }

    // epilogue
#pragma unroll
    for (int mt = 0; mt < 2; ++mt) {
        const int r0 = m0 + wm * 32 + mt * 16 + gid;
#pragma unroll
        for (int nt = 0; nt < 8; ++nt) {
            const int cl = wn * 64 + nt * 8 + 2 * tig;
            const float b0 = sbias[cl], b1 = sbias[cl + 1];
            if (r0 < n) {
                float2 v = make_float2(acc[mt][nt][0] + b0, acc[mt][nt][1] + b1);
                *(float2*)(out + (size_t)r0 * FEAT + by * 128 + cl) = v;
            }
            if (r0 + 8 < n) {
                float2 v = make_float2(acc[mt][nt][2] + b0, acc[mt][nt][3] + b1);
                *(float2*)(out + (size_t)(r0 + 8) * FEAT + by * 128 + cl) = v;
            }
        }
    }
}

// ---------------------------------------------------------------------------
extern "C" void kernel_launch(void* const* d_in, const int* in_sizes, int n_in,
                              void* d_out, int out_size) {
    const float* x      = (const float*)d_in[0];
    const void*  ei     = d_in[1];
    const float* Wsrel  = (const float*)d_in[2];
    const float* Wsroot = (const float*)d_in[3];
    const float* bs     = (const float*)d_in[4];
    const float* Wvrel  = (const float*)d_in[5];
    const float* Wvroot = (const float*)d_in[6];
    float*       out    = (float*)d_out;

    const int n = in_sizes[0] / FEAT;        // 10000
    const int E = in_sizes[1] / 2;           // 160000

    // CSR build
    prep_kernel<<<(n + 255) / 256, 256>>>((const long long*)ei, (long long)n, n);
    hist_kernel<<<(E / 4 + 255) / 256, 256>>>(ei, E);
    scan_kernel<<<1, 1024>>>(n);
    fill_kernel<<<(E / 4 + 255) / 256, 256>>>(ei, E);

    // Gather aggregation (1 warp / node)
    gather_kernel<<<(n * 32 + 255) / 256, 256>>>(x, n);

    // GEMM (R4 shape, heavy-first 1D grid)
    const int nm = (n + 127) / 128;          // 79 M-tiles
    mma_gemm_kernel<<<4 * nm, 256>>>(x, Wsrel, Wsroot, bs,
                                     Wvrel, Wvroot, out, n, nm);
}